// round 3
// baseline (speedup 1.0000x reference)
#include <cuda_runtime.h>
#include <cuda_bf16.h>

// SHEmbed: out[b,c] = clip( sum_j SH_j(ray_dir[b]) * sh_data[y[b], x[b], j, c], 0, 1 )
// L=3 -> 16 basis functions, 3 channels. H=W=1024, B=1048576.
//
// Inputs (metadata order): y:int32[B], x:int32[B], ray_dir:f32[B,3], sh_data:f32[H,W,16,3]
// Output: f32[B,3]

#define SH_B 1048576
#define SH_W 1024

__global__ __launch_bounds__(256)
void SHEmbed_69406671503663_kernel(const int* __restrict__ ys,
                                   const int* __restrict__ xs,
                                   const float* __restrict__ dir,
                                   const float* __restrict__ sh,
                                   float* __restrict__ out,
                                   int n)
{
    int i = blockIdx.x * blockDim.x + threadIdx.x;
    if (i >= n) return;

    // --- direction (normalized, matching reference's r = |d| + 1e-14) ---
    float dx = dir[3 * i + 0];
    float dy = dir[3 * i + 1];
    float dz = dir[3 * i + 2];
    float inv = 1.0f / (sqrtf(fmaf(dx, dx, fmaf(dy, dy, dz * dz))) + 1e-14f);
    float x = dx * inv, y = dy * inv, z = dz * inv;
    float xx = x * x, yy = y * y, zz = z * z;

    // --- closed-form real SH basis, L=3, with reference's (-1)^m sign convention ---
    float b[16];
    b[0]  =  0.28209479177387814f;
    b[1]  = -0.4886025119029199f * y;
    b[2]  =  0.4886025119029199f * z;
    b[3]  = -0.4886025119029199f * x;
    b[4]  =  1.0925484305920792f * x * y;
    b[5]  = -1.0925484305920792f * y * z;
    b[6]  =  0.31539156525252005f * (3.0f * zz - 1.0f);
    b[7]  = -1.0925484305920792f * x * z;
    b[8]  =  0.5462742152960396f * (xx - yy);
    b[9]  = -0.5900435899266435f * y * (3.0f * xx - yy);
    b[10] =  2.890611442640554f  * x * y * z;
    b[11] = -0.4570457994644658f * y * (5.0f * zz - 1.0f);
    b[12] =  0.3731763325901154f * z * (5.0f * zz - 3.0f);
    b[13] = -0.4570457994644658f * x * (5.0f * zz - 1.0f);
    b[14] =  1.445305721320277f  * z * (xx - yy);
    b[15] = -0.5900435899266435f * x * (xx - 3.0f * yy);

    // --- gather 48 floats (192 B, contiguous, 16B-aligned) and fuse the dot ---
    size_t cell = ((size_t)ys[i] * SH_W + (size_t)xs[i]) * 48u;
    const float4* __restrict__ cp = reinterpret_cast<const float4*>(sh + cell);

    float acc0 = 0.f, acc1 = 0.f, acc2 = 0.f;
    #pragma unroll
    for (int q = 0; q < 12; q++) {
        float4 v = cp[q];
        float vv0 = v.x, vv1 = v.y, vv2 = v.z, vv3 = v.w;
        // float index f = 4q + t maps to (j, ch) = (f/3, f%3), compile-time per (q,t)
        {
            const int f0 = 4 * q + 0, f1 = 4 * q + 1, f2 = 4 * q + 2, f3 = 4 * q + 3;
            // t = 0
            if      (f0 % 3 == 0) acc0 = fmaf(b[f0 / 3], vv0, acc0);
            else if (f0 % 3 == 1) acc1 = fmaf(b[f0 / 3], vv0, acc1);
            else                  acc2 = fmaf(b[f0 / 3], vv0, acc2);
            // t = 1
            if      (f1 % 3 == 0) acc0 = fmaf(b[f1 / 3], vv1, acc0);
            else if (f1 % 3 == 1) acc1 = fmaf(b[f1 / 3], vv1, acc1);
            else                  acc2 = fmaf(b[f1 / 3], vv1, acc2);
            // t = 2
            if      (f2 % 3 == 0) acc0 = fmaf(b[f2 / 3], vv2, acc0);
            else if (f2 % 3 == 1) acc1 = fmaf(b[f2 / 3], vv2, acc1);
            else                  acc2 = fmaf(b[f2 / 3], vv2, acc2);
            // t = 3
            if      (f3 % 3 == 0) acc0 = fmaf(b[f3 / 3], vv3, acc0);
            else if (f3 % 3 == 1) acc1 = fmaf(b[f3 / 3], vv3, acc1);
            else                  acc2 = fmaf(b[f3 / 3], vv3, acc2);
        }
    }

    out[3 * i + 0] = fminf(fmaxf(acc0, 0.0f), 1.0f);
    out[3 * i + 1] = fminf(fmaxf(acc1, 0.0f), 1.0f);
    out[3 * i + 2] = fminf(fmaxf(acc2, 0.0f), 1.0f);
}

extern "C" void kernel_launch(void* const* d_in, const int* in_sizes, int n_in,
                              void* d_out, int out_size)
{
    const int*   ys  = (const int*)d_in[0];
    const int*   xs  = (const int*)d_in[1];
    const float* dir = (const float*)d_in[2];
    const float* sh  = (const float*)d_in[3];
    float*       out = (float*)d_out;

    int n = in_sizes[0];  // B rays
    int threads = 256;
    int blocks = (n + threads - 1) / threads;
    SHEmbed_69406671503663_kernel<<<blocks, threads>>>(ys, xs, dir, sh, out, n);
}